// round 2
// baseline (speedup 1.0000x reference)
#include <cuda_runtime.h>
#include <math.h>

// Problem dims (fixed by the reference)
#define BATCH  16
#define NSEQ   4096
#define DDIM   512
#define MTOT   (BATCH*NSEQ)          // 65536 rows
#define CHAINS (BATCH*DDIM)          // 8192 scan chains
#define SEGLEN 16
#define NSEG   (NSEQ/SEGLEN)         // 256 segments per chain
#define SEGTOT (NSEG*CHAINS)         // 2097152 (chain,seg) pairs
#define EPSV   1e-6f

// ---------------- device scratch (allocation-free rule: device globals) ----------
__device__ float g_su  [MTOT*DDIM];   // silu(u)
__device__ float g_lam [MTOT*DDIM];   // lower-bounded forget gate
__device__ float g_gate[MTOT*DDIM];   // sigmoid output gate
__device__ float g_hf  [MTOT*DDIM];   // forward local scan
__device__ float g_hr  [MTOT*DDIM];   // reverse local scan
__device__ float g_h   [MTOT*DDIM];   // h = fwd + rev (corrected)
__device__ float g_hn  [MTOT*DDIM];   // normalized * gate
__device__ float g_aggA [SEGTOT];     // per-segment prod(lam)
__device__ float g_aggBf[SEGTOT];     // per-segment fwd end state
__device__ float g_aggBr[SEGTOT];     // per-segment rev end state
__device__ float g_cf   [SEGTOT];     // fwd carry into segment
__device__ float g_cr   [SEGTOT];     // rev carry into segment

__device__ __forceinline__ float sigm(float x) { return 1.0f / (1.0f + __expf(-x)); }

// =================================================================================
// GEMM 1: P = x @ [W_in | W_gate] + bias, fused activations in epilogue.
// Columns [0,512)   -> silu(u)       -> g_su
// Columns [512,1024)-> lam(f)        -> g_lam
// Columns [1024,1536)-> sigmoid(g)   -> g_gate
// 128x128x16 tiles, 256 threads, 8x8 register blocking.
// =================================================================================
__global__ __launch_bounds__(256) void gemm_in_kernel(
    const float* __restrict__ X, const float* __restrict__ Win,
    const float* __restrict__ bin, const float* __restrict__ Wg,
    const float* __restrict__ bg, const float* __restrict__ lbp)
{
    const int BK = 16;
    __shared__ float As[16][128];
    __shared__ float Bs[16][128];
    const int tid = threadIdx.x;
    const int r0 = blockIdx.y * 128;
    const int c0 = blockIdx.x * 128;   // 0..1535

    const float* W; const float* bias; int ldw, wc0, mode;
    if (c0 < 2 * DDIM) { W = Win; ldw = 2 * DDIM; wc0 = c0;          bias = bin; mode = (c0 < DDIM) ? 0 : 1; }
    else               { W = Wg;  ldw = DDIM;     wc0 = c0 - 2*DDIM; bias = bg;  mode = 2; }

    const int rbase = (tid >> 4) << 3;
    const int cbase = (tid & 15) << 3;

    float acc[8][8];
    #pragma unroll
    for (int i = 0; i < 8; i++)
        #pragma unroll
        for (int j = 0; j < 8; j++) acc[i][j] = 0.0f;

    for (int k0 = 0; k0 < DDIM; k0 += BK) {
        #pragma unroll
        for (int q = tid; q < 512; q += 256) {
            int row = q >> 2, kq = (q & 3) << 2;
            float4 v = *(const float4*)(X + (size_t)(r0 + row) * DDIM + k0 + kq);
            As[kq + 0][row] = v.x; As[kq + 1][row] = v.y;
            As[kq + 2][row] = v.z; As[kq + 3][row] = v.w;
        }
        #pragma unroll
        for (int q = tid; q < 512; q += 256) {
            int kr = q >> 5, cq = (q & 31) << 2;
            *(float4*)&Bs[kr][cq] = *(const float4*)(W + (size_t)(k0 + kr) * ldw + wc0 + cq);
        }
        __syncthreads();
        #pragma unroll
        for (int k = 0; k < BK; k++) {
            float a[8], b[8];
            *(float4*)(a)     = *(float4*)&As[k][rbase];
            *(float4*)(a + 4) = *(float4*)&As[k][rbase + 4];
            *(float4*)(b)     = *(float4*)&Bs[k][cbase];
            *(float4*)(b + 4) = *(float4*)&Bs[k][cbase + 4];
            #pragma unroll
            for (int i = 0; i < 8; i++)
                #pragma unroll
                for (int j = 0; j < 8; j++) acc[i][j] += a[i] * b[j];
        }
        __syncthreads();
    }

    const float lb = lbp[0];
    float bv[8];
    #pragma unroll
    for (int j = 0; j < 8; j++) bv[j] = bias[wc0 + cbase + j];
    const int ocol = ((mode == 0) ? c0 : (mode == 1) ? (c0 - DDIM) : (c0 - 2 * DDIM)) + cbase;
    float* outp = (mode == 0) ? g_su : (mode == 1) ? g_lam : g_gate;

    #pragma unroll
    for (int i = 0; i < 8; i++) {
        int m = r0 + rbase + i;
        float o[8];
        #pragma unroll
        for (int j = 0; j < 8; j++) {
            float p = acc[i][j] + bv[j];
            if (mode == 0)      o[j] = p * sigm(p);                 // silu(u)
            else if (mode == 1) o[j] = lb + (1.0f - lb) * sigm(p);  // lam
            else                o[j] = sigm(p);                     // gate
        }
        float* dst = outp + (size_t)m * DDIM + ocol;
        *(float4*)(dst)     = make_float4(o[0], o[1], o[2], o[3]);
        *(float4*)(dst + 4) = make_float4(o[4], o[5], o[6], o[7]);
    }
}

// =================================================================================
// Scan phase 1: per-(chain,segment) local fwd+rev scans with h0=0, plus aggregates
// (A = prod(lam) over segment, Bf/Br = end states). SEGLEN=16 values live in regs.
// =================================================================================
__global__ __launch_bounds__(256) void scan_phase1()
{
    int t = blockIdx.x * blockDim.x + threadIdx.x;   // [0, SEGTOT)
    int chain = t % CHAINS;                          // b*DDIM + d (coalesced in d)
    int seg   = t / CHAINS;
    int d = chain % DDIM, b = chain / DDIM;
    size_t base = ((size_t)(b * NSEQ + seg * SEGLEN)) * DDIM + d;

    float l[SEGLEN], v[SEGLEN];
    #pragma unroll
    for (int i = 0; i < SEGLEN; i++) {
        size_t idx = base + (size_t)i * DDIM;
        float li = g_lam[idx];
        float si = g_su[idx];
        l[i] = li;
        v[i] = (1.0f - li) * si;
    }
    float h = 0.0f, P = 1.0f;
    #pragma unroll
    for (int i = 0; i < SEGLEN; i++) {
        h = l[i] * h + v[i];
        g_hf[base + (size_t)i * DDIM] = h;
        P *= l[i];
    }
    float hr = 0.0f;
    #pragma unroll
    for (int i = SEGLEN - 1; i >= 0; i--) {
        hr = l[i] * hr + v[i];
        g_hr[base + (size_t)i * DDIM] = hr;
    }
    size_t aidx = (size_t)seg * CHAINS + chain;
    g_aggA [aidx] = P;
    g_aggBf[aidx] = h;
    g_aggBr[aidx] = hr;
}

// =================================================================================
// Scan phase 2: scan the 256 segment aggregates per chain (both directions).
// carry entering each segment is stored.
// =================================================================================
__global__ __launch_bounds__(256) void scan_phase2()
{
    int c = blockIdx.x * blockDim.x + threadIdx.x;   // [0, CHAINS)
    float carry = 0.0f;
    for (int s = 0; s < NSEG; s++) {
        size_t a = (size_t)s * CHAINS + c;
        g_cf[a] = carry;
        carry = g_aggA[a] * carry + g_aggBf[a];
    }
    carry = 0.0f;
    for (int s = NSEG - 1; s >= 0; s--) {
        size_t a = (size_t)s * CHAINS + c;
        g_cr[a] = carry;
        carry = g_aggA[a] * carry + g_aggBr[a];
    }
}

// =================================================================================
// Scan phase 3: apply carries. h[t] = hf_loc[t] + cf*prefixprod(lam)
//                                   + hr_loc[t] + cr*suffixprod(lam)
// Running products underflow gracefully to 0 (correction is negligible there).
// =================================================================================
__global__ __launch_bounds__(256) void scan_phase3()
{
    int t = blockIdx.x * blockDim.x + threadIdx.x;
    int chain = t % CHAINS;
    int seg   = t / CHAINS;
    int d = chain % DDIM, b = chain / DDIM;
    size_t base = ((size_t)(b * NSEQ + seg * SEGLEN)) * DDIM + d;
    size_t aidx = (size_t)seg * CHAINS + chain;
    float cf = g_cf[aidx];
    float cr = g_cr[aidx];

    float l[SEGLEN], hfc[SEGLEN];
    float P = 1.0f;
    #pragma unroll
    for (int i = 0; i < SEGLEN; i++) {
        size_t idx = base + (size_t)i * DDIM;
        l[i] = g_lam[idx];
        P *= l[i];
        hfc[i] = g_hf[idx] + cf * P;
    }
    float Q = 1.0f;
    #pragma unroll
    for (int i = SEGLEN - 1; i >= 0; i--) {
        size_t idx = base + (size_t)i * DDIM;
        Q *= l[i];
        g_h[idx] = hfc[i] + g_hr[idx] + cr * Q;
    }
}

// =================================================================================
// SimpleRMSNorm over D + output gate: hn = h * rsqrt(mean(h^2)+eps) * g.
// One warp per row (D=512 -> 16 floats/lane, float4 vectorized).
// =================================================================================
__global__ __launch_bounds__(256) void rms_gate_kernel()
{
    int warp = threadIdx.x >> 5, lane = threadIdx.x & 31;
    int row = blockIdx.x * 8 + warp;
    size_t base = (size_t)row * DDIM + lane * 4;

    float4 hv[4];
    float ss = 0.0f;
    #pragma unroll
    for (int j = 0; j < 4; j++) {
        hv[j] = *(const float4*)&g_h[base + j * 128];
        ss += hv[j].x * hv[j].x + hv[j].y * hv[j].y + hv[j].z * hv[j].z + hv[j].w * hv[j].w;
    }
    #pragma unroll
    for (int o = 16; o > 0; o >>= 1) ss += __shfl_xor_sync(0xffffffff, ss, o);
    float scale = rsqrtf(ss * (1.0f / DDIM) + EPSV);

    #pragma unroll
    for (int j = 0; j < 4; j++) {
        float4 gv = *(const float4*)&g_gate[base + j * 128];
        float4 o4;
        o4.x = hv[j].x * scale * gv.x;
        o4.y = hv[j].y * scale * gv.y;
        o4.z = hv[j].z * scale * gv.z;
        o4.w = hv[j].w * scale * gv.w;
        *(float4*)&g_hn[base + j * 128] = o4;
    }
}

// =================================================================================
// GEMM 2: out = hn @ W_out + b_out. Same tiling as GEMM 1.
// =================================================================================
__global__ __launch_bounds__(256) void gemm_out_kernel(
    const float* __restrict__ Wout, const float* __restrict__ bout,
    float* __restrict__ out)
{
    const int BK = 16;
    __shared__ float As[16][128];
    __shared__ float Bs[16][128];
    const int tid = threadIdx.x;
    const int r0 = blockIdx.y * 128;
    const int c0 = blockIdx.x * 128;   // 0..511

    const int rbase = (tid >> 4) << 3;
    const int cbase = (tid & 15) << 3;

    float acc[8][8];
    #pragma unroll
    for (int i = 0; i < 8; i++)
        #pragma unroll
        for (int j = 0; j < 8; j++) acc[i][j] = 0.0f;

    for (int k0 = 0; k0 < DDIM; k0 += BK) {
        #pragma unroll
        for (int q = tid; q < 512; q += 256) {
            int row = q >> 2, kq = (q & 3) << 2;
            float4 v = *(const float4*)(g_hn + (size_t)(r0 + row) * DDIM + k0 + kq);
            As[kq + 0][row] = v.x; As[kq + 1][row] = v.y;
            As[kq + 2][row] = v.z; As[kq + 3][row] = v.w;
        }
        #pragma unroll
        for (int q = tid; q < 512; q += 256) {
            int kr = q >> 5, cq = (q & 31) << 2;
            *(float4*)&Bs[kr][cq] = *(const float4*)(Wout + (size_t)(k0 + kr) * DDIM + c0 + cq);
        }
        __syncthreads();
        #pragma unroll
        for (int k = 0; k < BK; k++) {
            float a[8], b[8];
            *(float4*)(a)     = *(float4*)&As[k][rbase];
            *(float4*)(a + 4) = *(float4*)&As[k][rbase + 4];
            *(float4*)(b)     = *(float4*)&Bs[k][cbase];
            *(float4*)(b + 4) = *(float4*)&Bs[k][cbase + 4];
            #pragma unroll
            for (int i = 0; i < 8; i++)
                #pragma unroll
                for (int j = 0; j < 8; j++) acc[i][j] += a[i] * b[j];
        }
        __syncthreads();
    }

    float bv[8];
    #pragma unroll
    for (int j = 0; j < 8; j++) bv[j] = bout[c0 + cbase + j];
    #pragma unroll
    for (int i = 0; i < 8; i++) {
        int m = r0 + rbase + i;
        float o[8];
        #pragma unroll
        for (int j = 0; j < 8; j++) o[j] = acc[i][j] + bv[j];
        float* dst = out + (size_t)m * DDIM + c0 + cbase;
        *(float4*)(dst)     = make_float4(o[0], o[1], o[2], o[3]);
        *(float4*)(dst + 4) = make_float4(o[4], o[5], o[6], o[7]);
    }
}

// =================================================================================
// Launch: x, lower_bound, W_in, b_in, W_gate, b_gate, W_out, b_out
// =================================================================================
extern "C" void kernel_launch(void* const* d_in, const int* in_sizes, int n_in,
                              void* d_out, int out_size)
{
    const float* x    = (const float*)d_in[0];
    const float* lb   = (const float*)d_in[1];
    const float* Win  = (const float*)d_in[2];
    const float* bin  = (const float*)d_in[3];
    const float* Wg   = (const float*)d_in[4];
    const float* bg   = (const float*)d_in[5];
    const float* Wout = (const float*)d_in[6];
    const float* bout = (const float*)d_in[7];
    float* out = (float*)d_out;

    dim3 g1(12, MTOT / 128);
    gemm_in_kernel<<<g1, 256>>>(x, Win, bin, Wg, bg, lb);
    scan_phase1<<<SEGTOT / 256, 256>>>();
    scan_phase2<<<CHAINS / 256, 256>>>();
    scan_phase3<<<SEGTOT / 256, 256>>>();
    rms_gate_kernel<<<MTOT / 8, 256>>>();
    dim3 g2(4, MTOT / 128);
    gemm_out_kernel<<<g2, 256>>>(Wout, bout, out);
}

// round 3
// speedup vs baseline: 1.9285x; 1.9285x over previous
#include <cuda_runtime.h>
#include <cuda_bf16.h>
#include <stdint.h>
#include <math.h>

// Problem dims (fixed by the reference)
#define BATCH  16
#define NSEQ   4096
#define DDIM   512
#define MTOT   (BATCH*NSEQ)          // 65536 rows
#define CHAINS (BATCH*DDIM)          // 8192 scan chains
#define SEGLEN 16
#define NSEG   (NSEQ/SEGLEN)         // 256 segments per chain
#define SEGTOT (NSEG*CHAINS)         // 2097152
#define EPSV   1e-6f

#define N1     (3*DDIM)              // 1536 fused output cols of GEMM1

// GEMM tiling
#define BM 128
#define BN 128
#define KC 16                        // k per pipeline chunk (1 mma k-step)
#define LDT 24                       // padded smem row (bf16 elems): 48B stride
#define TILE_ELEMS (BM*LDT)          // 3072 bf16 per array
#define ARR_BYTES  (TILE_ELEMS*2)    // 6144
#define STAGE_BYTES (4*ARR_BYTES)    // 24576
#define NCHUNK (DDIM/KC)             // 32

// ---------------- device scratch ----------------
__device__ __nv_bfloat16 g_xhi [MTOT*DDIM];
__device__ __nv_bfloat16 g_xlo [MTOT*DDIM];
__device__ __nv_bfloat16 g_b1hi[N1*DDIM];     // [n][k] transposed W_in|W_gate
__device__ __nv_bfloat16 g_b1lo[N1*DDIM];
__device__ __nv_bfloat16 g_b2hi[DDIM*DDIM];   // [n][k] transposed W_out
__device__ __nv_bfloat16 g_b2lo[DDIM*DDIM];
__device__ float g_su  [MTOT*DDIM];
__device__ float g_lam [MTOT*DDIM];
__device__ float g_gate[MTOT*DDIM];
__device__ float g_h   [MTOT*DDIM];
__device__ __nv_bfloat16 g_hnhi[MTOT*DDIM];
__device__ __nv_bfloat16 g_hnlo[MTOT*DDIM];
__device__ float g_aggA [SEGTOT];
__device__ float g_aggBf[SEGTOT];
__device__ float g_aggBr[SEGTOT];
__device__ float g_cf   [SEGTOT];
__device__ float g_cr   [SEGTOT];

__device__ __forceinline__ float sigm(float x) { return 1.0f / (1.0f + __expf(-x)); }

__device__ __forceinline__ uint32_t pack_bf2(__nv_bfloat16 a, __nv_bfloat16 b) {
    return (uint32_t)__bfloat16_as_ushort(a) | ((uint32_t)__bfloat16_as_ushort(b) << 16);
}

// ---------------- PTX helpers ----------------
__device__ __forceinline__ void mma16816(float* c, const uint32_t* a, const uint32_t* b) {
    asm volatile(
        "mma.sync.aligned.m16n8k16.row.col.f32.bf16.bf16.f32 "
        "{%0,%1,%2,%3}, {%4,%5,%6,%7}, {%8,%9}, {%0,%1,%2,%3};"
        : "+f"(c[0]), "+f"(c[1]), "+f"(c[2]), "+f"(c[3])
        : "r"(a[0]), "r"(a[1]), "r"(a[2]), "r"(a[3]), "r"(b[0]), "r"(b[1]));
}
__device__ __forceinline__ void ldsm4(uint32_t* r, uint32_t addr) {
    asm volatile("ldmatrix.sync.aligned.m8n8.x4.shared.b16 {%0,%1,%2,%3}, [%4];"
                 : "=r"(r[0]), "=r"(r[1]), "=r"(r[2]), "=r"(r[3]) : "r"(addr));
}
__device__ __forceinline__ void cpasync16(uint32_t saddr, const void* g) {
    asm volatile("cp.async.cg.shared.global [%0], [%1], 16;" :: "r"(saddr), "l"(g));
}
__device__ __forceinline__ void cp_commit() { asm volatile("cp.async.commit_group;"); }
__device__ __forceinline__ void cp_wait1()  { asm volatile("cp.async.wait_group 1;"); }
__device__ __forceinline__ void cp_wait0()  { asm volatile("cp.async.wait_group 0;"); }

// =================================================================================
// split conversion kernels
// =================================================================================
__global__ __launch_bounds__(256) void convert_x_kernel(const float* __restrict__ X)
{
    int i = blockIdx.x * 256 + threadIdx.x;            // over float4s
    float4 v = ((const float4*)X)[i];
    __nv_bfloat16 h0 = __float2bfloat16_rn(v.x);
    __nv_bfloat16 h1 = __float2bfloat16_rn(v.y);
    __nv_bfloat16 h2 = __float2bfloat16_rn(v.z);
    __nv_bfloat16 h3 = __float2bfloat16_rn(v.w);
    __nv_bfloat16 l0 = __float2bfloat16_rn(v.x - __bfloat162float(h0));
    __nv_bfloat16 l1 = __float2bfloat16_rn(v.y - __bfloat162float(h1));
    __nv_bfloat16 l2 = __float2bfloat16_rn(v.z - __bfloat162float(h2));
    __nv_bfloat16 l3 = __float2bfloat16_rn(v.w - __bfloat162float(h3));
    uint2 uh; uh.x = pack_bf2(h0, h1); uh.y = pack_bf2(h2, h3);
    uint2 ul; ul.x = pack_bf2(l0, l1); ul.y = pack_bf2(l2, l3);
    ((uint2*)g_xhi)[i] = uh;
    ((uint2*)g_xlo)[i] = ul;
}

__global__ __launch_bounds__(256) void convert_w1_kernel(
    const float* __restrict__ Win, const float* __restrict__ Wg)
{
    int idx = blockIdx.x * 256 + threadIdx.x;          // [0, N1*DDIM)
    int n = idx / DDIM, k = idx % DDIM;
    float w = (n < 2 * DDIM) ? Win[(size_t)k * (2 * DDIM) + n]
                             : Wg [(size_t)k * DDIM + (n - 2 * DDIM)];
    __nv_bfloat16 h = __float2bfloat16_rn(w);
    __nv_bfloat16 l = __float2bfloat16_rn(w - __bfloat162float(h));
    g_b1hi[idx] = h; g_b1lo[idx] = l;
}

__global__ __launch_bounds__(256) void convert_w2_kernel(const float* __restrict__ Wout)
{
    int idx = blockIdx.x * 256 + threadIdx.x;          // [0, DDIM*DDIM)
    int n = idx / DDIM, k = idx % DDIM;
    float w = Wout[(size_t)k * DDIM + n];
    __nv_bfloat16 h = __float2bfloat16_rn(w);
    __nv_bfloat16 l = __float2bfloat16_rn(w - __bfloat162float(h));
    g_b2hi[idx] = h; g_b2lo[idx] = l;
}

// =================================================================================
// Tensor-core GEMM: C = A(M x 512) * Bt(N x 512)^T with 3x bf16-split emulation.
// MODE 0: N=1536 fused [u|f|gate] epilogue -> g_su/g_lam/g_gate
// MODE 1: N=512, out = C + b_out -> outp
// =================================================================================
template<int MODE>
__global__ __launch_bounds__(256) void gemm_tc(
    const __nv_bfloat16* __restrict__ Ahi, const __nv_bfloat16* __restrict__ Alo,
    const __nv_bfloat16* __restrict__ Bhi, const __nv_bfloat16* __restrict__ Blo,
    const float* __restrict__ bias_a, const float* __restrict__ bias_b,
    const float* __restrict__ lbp, float* __restrict__ outp)
{
    __shared__ __nv_bfloat16 tiles[2 * 4 * TILE_ELEMS];   // 48KB
    const uint32_t sb = (uint32_t)__cvta_generic_to_shared(tiles);
    const int tid = threadIdx.x;
    const int r0 = blockIdx.y * BM;
    const int c0 = blockIdx.x * BN;

    float acc[4][4][4];
    #pragma unroll
    for (int i = 0; i < 4; i++)
        #pragma unroll
        for (int j = 0; j < 4; j++)
            #pragma unroll
            for (int q = 0; q < 4; q++) acc[i][j][q] = 0.0f;

    const int lrow = tid >> 1;           // 0..127
    const int lseg = tid & 1;            // 0..1  (16B each, 2*16B = 32B = 16 bf16)
    const size_t gA = (size_t)(r0 + lrow) * DDIM + lseg * 8;
    const size_t gB = (size_t)(c0 + lrow) * DDIM + lseg * 8;
    const uint32_t sOff = lrow * 48 + lseg * 16;

    // prologue: chunk 0 -> stage 0
    {
        cpasync16(sb + 0 * STAGE_BYTES + 0 * ARR_BYTES + sOff, Ahi + gA);
        cpasync16(sb + 0 * STAGE_BYTES + 1 * ARR_BYTES + sOff, Alo + gA);
        cpasync16(sb + 0 * STAGE_BYTES + 2 * ARR_BYTES + sOff, Bhi + gB);
        cpasync16(sb + 0 * STAGE_BYTES + 3 * ARR_BYTES + sOff, Blo + gB);
        cp_commit();
    }

    const int lane = tid & 31, wid = tid >> 5;
    const int wm = wid >> 2, wn = wid & 3;
    const int sub = lane >> 3, lr = lane & 7;

    for (int c = 0; c < NCHUNK; c++) {
        if (c + 1 < NCHUNK) {
            const uint32_t st = (uint32_t)((c + 1) & 1) * STAGE_BYTES;
            const int k0 = (c + 1) * KC;
            cpasync16(sb + st + 0 * ARR_BYTES + sOff, Ahi + gA + k0);
            cpasync16(sb + st + 1 * ARR_BYTES + sOff, Alo + gA + k0);
            cpasync16(sb + st + 2 * ARR_BYTES + sOff, Bhi + gB + k0);
            cpasync16(sb + st + 3 * ARR_BYTES + sOff, Blo + gB + k0);
            cp_commit();
            cp_wait1();
        } else {
            cp_wait0();
        }
        __syncthreads();

        const uint32_t st = (uint32_t)(c & 1) * STAGE_BYTES;
        const uint32_t sAhi = sb + st;
        const uint32_t sAlo = sAhi + ARR_BYTES;
        const uint32_t sBhi = sAlo + ARR_BYTES;
        const uint32_t sBlo = sBhi + ARR_BYTES;

        // B fragments: 2 x ldmatrix.x4 per split cover 4 n-tiles of 8
        uint32_t bhi[4][2], blo[4][2];
        #pragma unroll
        for (int p = 0; p < 2; p++) {
            const uint32_t bo = (uint32_t)(wn * 32 + p * 16 + lr + (sub >> 1) * 8) * 48
                              + (uint32_t)(sub & 1) * 16;
            uint32_t t4[4];
            ldsm4(t4, sBhi + bo);
            bhi[2*p][0] = t4[0]; bhi[2*p][1] = t4[1]; bhi[2*p+1][0] = t4[2]; bhi[2*p+1][1] = t4[3];
            ldsm4(t4, sBlo + bo);
            blo[2*p][0] = t4[0]; blo[2*p][1] = t4[1]; blo[2*p+1][0] = t4[2]; blo[2*p+1][1] = t4[3];
        }
        #pragma unroll
        for (int mi = 0; mi < 4; mi++) {
            const uint32_t ao = (uint32_t)(wm * 64 + mi * 16 + lr + (sub & 1) * 8) * 48
                              + (uint32_t)(sub >> 1) * 16;
            uint32_t ahi[4], alo[4];
            ldsm4(ahi, sAhi + ao);
            ldsm4(alo, sAlo + ao);
            #pragma unroll
            for (int ni = 0; ni < 4; ni++) {
                mma16816(acc[mi][ni], ahi, bhi[ni]);
                mma16816(acc[mi][ni], ahi, blo[ni]);
                mma16816(acc[mi][ni], alo, bhi[ni]);
            }
        }
        __syncthreads();
    }

    // -------- epilogue --------
    const int g = lane >> 2, t = lane & 3;
    float lb = 0.0f;
    if (MODE == 0) lb = lbp[0];

    #pragma unroll
    for (int mi = 0; mi < 4; mi++) {
        const int m0 = r0 + wm * 64 + mi * 16 + g;
        #pragma unroll
        for (int ni = 0; ni < 4; ni++) {
            const int nc = c0 + wn * 32 + ni * 8 + t * 2;
            float p0 = acc[mi][ni][0], p1 = acc[mi][ni][1];
            float p2 = acc[mi][ni][2], p3 = acc[mi][ni][3];
            if (MODE == 1) {
                const float b0 = bias_a[nc], b1 = bias_a[nc + 1];
                *(float2*)&outp[(size_t)m0 * DDIM + nc]       = make_float2(p0 + b0, p1 + b1);
                *(float2*)&outp[(size_t)(m0+8) * DDIM + nc]   = make_float2(p2 + b0, p3 + b1);
            } else {
                const int reg = nc >> 9;           // 0=u, 1=f, 2=gate
                const int lc = nc & 511;
                float b0, b1; float* dst;
                if (reg < 2) { b0 = bias_a[nc]; b1 = bias_a[nc + 1]; }
                else         { b0 = bias_b[lc]; b1 = bias_b[lc + 1]; }
                p0 += b0; p1 += b1; p2 += b0; p3 += b1;
                float o0, o1, o2, o3;
                if (reg == 0) {
                    o0 = p0 * sigm(p0); o1 = p1 * sigm(p1);
                    o2 = p2 * sigm(p2); o3 = p3 * sigm(p3);
                    dst = g_su;
                } else if (reg == 1) {
                    const float w = 1.0f - lb;
                    o0 = lb + w * sigm(p0); o1 = lb + w * sigm(p1);
                    o2 = lb + w * sigm(p2); o3 = lb + w * sigm(p3);
                    dst = g_lam;
                } else {
                    o0 = sigm(p0); o1 = sigm(p1); o2 = sigm(p2); o3 = sigm(p3);
                    dst = g_gate;
                }
                *(float2*)&dst[(size_t)m0 * DDIM + lc]     = make_float2(o0, o1);
                *(float2*)&dst[(size_t)(m0+8) * DDIM + lc] = make_float2(o2, o3);
            }
        }
    }
}

// =================================================================================
// Scan phase 1: per-(chain,segment) aggregates only (A, Bf, Br). No hf/hr stores.
// =================================================================================
__global__ __launch_bounds__(256) void scan_phase1()
{
    int tt = blockIdx.x * blockDim.x + threadIdx.x;
    int chain = tt % CHAINS;
    int seg   = tt / CHAINS;
    int d = chain % DDIM, b = chain / DDIM;
    size_t base = ((size_t)(b * NSEQ + seg * SEGLEN)) * DDIM + d;

    float l[SEGLEN], v[SEGLEN];
    #pragma unroll
    for (int i = 0; i < SEGLEN; i++) {
        size_t idx = base + (size_t)i * DDIM;
        float li = g_lam[idx];
        float si = g_su[idx];
        l[i] = li;
        v[i] = (1.0f - li) * si;
    }
    float h = 0.0f, P = 1.0f;
    #pragma unroll
    for (int i = 0; i < SEGLEN; i++) { h = l[i] * h + v[i]; P *= l[i]; }
    float hr = 0.0f;
    #pragma unroll
    for (int i = SEGLEN - 1; i >= 0; i--) hr = l[i] * hr + v[i];

    size_t aidx = (size_t)seg * CHAINS + chain;
    g_aggA [aidx] = P;
    g_aggBf[aidx] = h;
    g_aggBr[aidx] = hr;
}

// =================================================================================
// Scan phase 2: scan segment aggregates per chain (both directions).
// =================================================================================
__global__ __launch_bounds__(256) void scan_phase2()
{
    int c = blockIdx.x * blockDim.x + threadIdx.x;
    float carry = 0.0f;
    #pragma unroll 8
    for (int s = 0; s < NSEG; s++) {
        size_t a = (size_t)s * CHAINS + c;
        g_cf[a] = carry;
        carry = g_aggA[a] * carry + g_aggBf[a];
    }
    carry = 0.0f;
    #pragma unroll 8
    for (int s = NSEG - 1; s >= 0; s--) {
        size_t a = (size_t)s * CHAINS + c;
        g_cr[a] = carry;
        carry = g_aggA[a] * carry + g_aggBr[a];
    }
}

// =================================================================================
// Scan phase 3: recompute local scans with carries folded into initial state.
// =================================================================================
__global__ __launch_bounds__(256) void scan_phase3()
{
    int tt = blockIdx.x * blockDim.x + threadIdx.x;
    int chain = tt % CHAINS;
    int seg   = tt / CHAINS;
    int d = chain % DDIM, b = chain / DDIM;
    size_t base = ((size_t)(b * NSEQ + seg * SEGLEN)) * DDIM + d;
    size_t aidx = (size_t)seg * CHAINS + chain;
    float cf = g_cf[aidx];
    float cr = g_cr[aidx];

    float l[SEGLEN], v[SEGLEN], hf[SEGLEN];
    #pragma unroll
    for (int i = 0; i < SEGLEN; i++) {
        size_t idx = base + (size_t)i * DDIM;
        float li = g_lam[idx];
        float si = g_su[idx];
        l[i] = li;
        v[i] = (1.0f - li) * si;
    }
    float h = cf;
    #pragma unroll
    for (int i = 0; i < SEGLEN; i++) { h = l[i] * h + v[i]; hf[i] = h; }
    float hr = cr;
    #pragma unroll
    for (int i = SEGLEN - 1; i >= 0; i--) {
        hr = l[i] * hr + v[i];
        g_h[base + (size_t)i * DDIM] = hf[i] + hr;
    }
}

// =================================================================================
// SimpleRMSNorm + output gate; writes bf16 hi/lo split of hn directly.
// =================================================================================
__global__ __launch_bounds__(256) void rms_gate_kernel()
{
    int warp = threadIdx.x >> 5, lane = threadIdx.x & 31;
    int row = blockIdx.x * 8 + warp;
    size_t base = (size_t)row * DDIM + lane * 4;

    float4 hv[4];
    float ss = 0.0f;
    #pragma unroll
    for (int j = 0; j < 4; j++) {
        hv[j] = *(const float4*)&g_h[base + j * 128];
        ss += hv[j].x * hv[j].x + hv[j].y * hv[j].y + hv[j].z * hv[j].z + hv[j].w * hv[j].w;
    }
    #pragma unroll
    for (int o = 16; o > 0; o >>= 1) ss += __shfl_xor_sync(0xffffffff, ss, o);
    float scale = rsqrtf(ss * (1.0f / DDIM) + EPSV);

    #pragma unroll
    for (int j = 0; j < 4; j++) {
        float4 gv = *(const float4*)&g_gate[base + j * 128];
        float o0 = hv[j].x * scale * gv.x;
        float o1 = hv[j].y * scale * gv.y;
        float o2 = hv[j].z * scale * gv.z;
        float o3 = hv[j].w * scale * gv.w;
        __nv_bfloat16 h0 = __float2bfloat16_rn(o0);
        __nv_bfloat16 h1 = __float2bfloat16_rn(o1);
        __nv_bfloat16 h2 = __float2bfloat16_rn(o2);
        __nv_bfloat16 h3 = __float2bfloat16_rn(o3);
        __nv_bfloat16 l0 = __float2bfloat16_rn(o0 - __bfloat162float(h0));
        __nv_bfloat16 l1 = __float2bfloat16_rn(o1 - __bfloat162float(h1));
        __nv_bfloat16 l2 = __float2bfloat16_rn(o2 - __bfloat162float(h2));
        __nv_bfloat16 l3 = __float2bfloat16_rn(o3 - __bfloat162float(h3));
        uint2 uh; uh.x = pack_bf2(h0, h1); uh.y = pack_bf2(h2, h3);
        uint2 ul; ul.x = pack_bf2(l0, l1); ul.y = pack_bf2(l2, l3);
        *(uint2*)&g_hnhi[base + j * 128] = uh;
        *(uint2*)&g_hnlo[base + j * 128] = ul;
    }
}

// =================================================================================
// Launch: x, lower_bound, W_in, b_in, W_gate, b_gate, W_out, b_out
// =================================================================================
extern "C" void kernel_launch(void* const* d_in, const int* in_sizes, int n_in,
                              void* d_out, int out_size)
{
    const float* x    = (const float*)d_in[0];
    const float* lb   = (const float*)d_in[1];
    const float* Win  = (const float*)d_in[2];
    const float* bin  = (const float*)d_in[3];
    const float* Wg   = (const float*)d_in[4];
    const float* bg   = (const float*)d_in[5];
    const float* Wout = (const float*)d_in[6];
    const float* bout = (const float*)d_in[7];
    float* out = (float*)d_out;

    __nv_bfloat16 *xhi, *xlo, *b1hi, *b1lo, *b2hi, *b2lo, *hnhi, *hnlo;
    cudaGetSymbolAddress((void**)&xhi,  g_xhi);
    cudaGetSymbolAddress((void**)&xlo,  g_xlo);
    cudaGetSymbolAddress((void**)&b1hi, g_b1hi);
    cudaGetSymbolAddress((void**)&b1lo, g_b1lo);
    cudaGetSymbolAddress((void**)&b2hi, g_b2hi);
    cudaGetSymbolAddress((void**)&b2lo, g_b2lo);
    cudaGetSymbolAddress((void**)&hnhi, g_hnhi);
    cudaGetSymbolAddress((void**)&hnlo, g_hnlo);

    convert_x_kernel<<<(MTOT * DDIM / 4) / 256, 256>>>(x);
    convert_w1_kernel<<<(N1 * DDIM) / 256, 256>>>(Win, Wg);
    convert_w2_kernel<<<(DDIM * DDIM) / 256, 256>>>(Wout);

    dim3 g1(N1 / BN, MTOT / BM);           // (12, 512)
    gemm_tc<0><<<g1, 256>>>(xhi, xlo, b1hi, b1lo, bin, bg, lb, nullptr);

    scan_phase1<<<SEGTOT / 256, 256>>>();
    scan_phase2<<<CHAINS / 256, 256>>>();
    scan_phase3<<<SEGTOT / 256, 256>>>();
    rms_gate_kernel<<<MTOT / 8, 256>>>();

    dim3 g2(DDIM / BN, MTOT / BM);         // (4, 512)
    gemm_tc<1><<<g2, 256>>>(hnhi, hnlo, b2hi, b2lo, bout, nullptr, nullptr, out);
}

// round 5
// speedup vs baseline: 2.0444x; 1.0601x over previous
#include <cuda_runtime.h>
#include <cuda_bf16.h>
#include <stdint.h>
#include <math.h>

// Problem dims (fixed by the reference)
#define BATCH  16
#define NSEQ   4096
#define DDIM   512
#define MTOT   (BATCH*NSEQ)          // 65536 rows
#define CHAINS (BATCH*DDIM)          // 8192 scan chains
#define SEGLEN 16
#define NSEG   (NSEQ/SEGLEN)         // 256
#define SEGTOT (NSEG*CHAINS)         // 2097152
#define EPSV   1e-6f
#define N1     (3*DDIM)              // 1536

// GEMM tiling (mma.sync path; tcgen05 blocked by compute_100 toolchain)
#define BM 128
#define BN 128
#define KC 16                        // k per pipeline chunk (1 mma k-step)
#define LDT 24                       // padded smem row (bf16): 48B stride
#define TILE_ELEMS (BM*LDT)          // 3072 bf16 per array
#define ARR_BYTES  (TILE_ELEMS*2)    // 6144
#define STAGE_BYTES (4*ARR_BYTES)    // 24576
#define NSTAGE 4
#define SMEM_REQ (NSTAGE*STAGE_BYTES) // 98304
#define NCHUNK (DDIM/KC)             // 32

// ---------------- device scratch ----------------
__device__ __nv_bfloat16 g_xhi [MTOT*DDIM];
__device__ __nv_bfloat16 g_xlo [MTOT*DDIM];
__device__ __nv_bfloat16 g_b1hi[N1*DDIM];     // [n][k] transposed W_in|W_gate
__device__ __nv_bfloat16 g_b1lo[N1*DDIM];
__device__ __nv_bfloat16 g_b2hi[DDIM*DDIM];   // [n][k] transposed W_out
__device__ __nv_bfloat16 g_b2lo[DDIM*DDIM];
__device__ float g_su  [MTOT*DDIM];
__device__ float g_lam [MTOT*DDIM];
__device__ float g_gate[MTOT*DDIM];
__device__ float g_h   [MTOT*DDIM];
__device__ __nv_bfloat16 g_hnhi[MTOT*DDIM];
__device__ __nv_bfloat16 g_hnlo[MTOT*DDIM];
__device__ float g_aggA [SEGTOT];
__device__ float g_aggBf[SEGTOT];
__device__ float g_aggBr[SEGTOT];
__device__ float g_cf   [SEGTOT];
__device__ float g_cr   [SEGTOT];

__device__ __forceinline__ float sigm(float x) { return 1.0f / (1.0f + __expf(-x)); }
__device__ __forceinline__ uint32_t pack_bf2(__nv_bfloat16 a, __nv_bfloat16 b) {
    return (uint32_t)__bfloat16_as_ushort(a) | ((uint32_t)__bfloat16_as_ushort(b) << 16);
}

// ---------------- PTX helpers ----------------
__device__ __forceinline__ void mma16816(float* c, const uint32_t* a, const uint32_t* b) {
    asm volatile(
        "mma.sync.aligned.m16n8k16.row.col.f32.bf16.bf16.f32 "
        "{%0,%1,%2,%3}, {%4,%5,%6,%7}, {%8,%9}, {%0,%1,%2,%3};"
        : "+f"(c[0]), "+f"(c[1]), "+f"(c[2]), "+f"(c[3])
        : "r"(a[0]), "r"(a[1]), "r"(a[2]), "r"(a[3]), "r"(b[0]), "r"(b[1]));
}
__device__ __forceinline__ void ldsm4(uint32_t* r, uint32_t addr) {
    asm volatile("ldmatrix.sync.aligned.m8n8.x4.shared.b16 {%0,%1,%2,%3}, [%4];"
                 : "=r"(r[0]), "=r"(r[1]), "=r"(r[2]), "=r"(r[3]) : "r"(addr));
}
__device__ __forceinline__ void cpasync16(uint32_t saddr, const void* g) {
    asm volatile("cp.async.cg.shared.global [%0], [%1], 16;" :: "r"(saddr), "l"(g));
}
__device__ __forceinline__ void cp_commit() { asm volatile("cp.async.commit_group;"); }
template<int N> __device__ __forceinline__ void cp_wait() {
    asm volatile("cp.async.wait_group %0;" :: "n"(N));
}

// ================= split conversion kernels =================
__global__ __launch_bounds__(256) void convert_x_kernel(const float* __restrict__ X)
{
    int i = blockIdx.x * 256 + threadIdx.x;            // over float4s
    float4 v = ((const float4*)X)[i];
    __nv_bfloat16 h0 = __float2bfloat16_rn(v.x), h1 = __float2bfloat16_rn(v.y);
    __nv_bfloat16 h2 = __float2bfloat16_rn(v.z), h3 = __float2bfloat16_rn(v.w);
    __nv_bfloat16 l0 = __float2bfloat16_rn(v.x - __bfloat162float(h0));
    __nv_bfloat16 l1 = __float2bfloat16_rn(v.y - __bfloat162float(h1));
    __nv_bfloat16 l2 = __float2bfloat16_rn(v.z - __bfloat162float(h2));
    __nv_bfloat16 l3 = __float2bfloat16_rn(v.w - __bfloat162float(h3));
    uint2 uh; uh.x = pack_bf2(h0, h1); uh.y = pack_bf2(h2, h3);
    uint2 ul; ul.x = pack_bf2(l0, l1); ul.y = pack_bf2(l2, l3);
    ((uint2*)g_xhi)[i] = uh;
    ((uint2*)g_xlo)[i] = ul;
}
__global__ __launch_bounds__(256) void convert_w1_kernel(
    const float* __restrict__ Win, const float* __restrict__ Wg)
{
    int idx = blockIdx.x * 256 + threadIdx.x;          // [0, N1*DDIM)
    int n = idx / DDIM, k = idx % DDIM;
    float w = (n < 2 * DDIM) ? Win[(size_t)k * (2 * DDIM) + n]
                             : Wg [(size_t)k * DDIM + (n - 2 * DDIM)];
    __nv_bfloat16 h = __float2bfloat16_rn(w);
    g_b1hi[idx] = h;
    g_b1lo[idx] = __float2bfloat16_rn(w - __bfloat162float(h));
}
__global__ __launch_bounds__(256) void convert_w2_kernel(const float* __restrict__ Wout)
{
    int idx = blockIdx.x * 256 + threadIdx.x;          // [0, DDIM*DDIM)
    int n = idx / DDIM, k = idx % DDIM;
    float w = Wout[(size_t)k * DDIM + n];
    __nv_bfloat16 h = __float2bfloat16_rn(w);
    g_b2hi[idx] = h;
    g_b2lo[idx] = __float2bfloat16_rn(w - __bfloat162float(h));
}

// =================================================================================
// mma.sync GEMM, 4-stage cp.async pipeline, one __syncthreads per chunk.
// C = A(M x 512) * Bt(N x 512)^T with 3x bf16-split emulation.
// MODE 0: N=1536 fused [u|f|gate] epilogue.  MODE 1: N=512, +bias -> outp.
// =================================================================================
template<int MODE>
__global__ void __launch_bounds__(256) gemm_tc(
    const __nv_bfloat16* __restrict__ Ahi, const __nv_bfloat16* __restrict__ Alo,
    const __nv_bfloat16* __restrict__ Bhi, const __nv_bfloat16* __restrict__ Blo,
    const float* __restrict__ bias_a, const float* __restrict__ bias_b,
    const float* __restrict__ lbp, float* __restrict__ outp)
{
    extern __shared__ __nv_bfloat16 tiles[];           // 4 stages x 24KB
    const uint32_t sb = (uint32_t)__cvta_generic_to_shared(tiles);
    const int tid = threadIdx.x;
    const int r0 = blockIdx.y * BM;
    const int c0 = blockIdx.x * BN;

    float acc[4][4][4];
    #pragma unroll
    for (int i = 0; i < 4; i++)
        #pragma unroll
        for (int j = 0; j < 4; j++)
            #pragma unroll
            for (int q = 0; q < 4; q++) acc[i][j][q] = 0.0f;

    const int lrow = tid >> 1;           // 0..127
    const int lseg = tid & 1;            // 16B halves of the 32B row
    const size_t gA = (size_t)(r0 + lrow) * DDIM + lseg * 8;
    const size_t gB = (size_t)(c0 + lrow) * DDIM + lseg * 8;
    const uint32_t sOff = lrow * 48 + lseg * 16;

    // prologue: chunks 0..2 -> stages 0..2, one commit group each
    #pragma unroll
    for (int p = 0; p < 3; p++) {
        const uint32_t st = sb + (uint32_t)p * STAGE_BYTES;
        const int k0 = p * KC;
        cpasync16(st + 0 * ARR_BYTES + sOff, Ahi + gA + k0);
        cpasync16(st + 1 * ARR_BYTES + sOff, Alo + gA + k0);
        cpasync16(st + 2 * ARR_BYTES + sOff, Bhi + gB + k0);
        cpasync16(st + 3 * ARR_BYTES + sOff, Blo + gB + k0);
        cp_commit();
    }

    const int lane = tid & 31, wid = tid >> 5;
    const int wm = wid >> 2, wn = wid & 3;
    const int sub = lane >> 3, lr = lane & 7;
    const uint32_t boBase = (uint32_t)(wn * 32 + lr + (sub >> 1) * 8) * 48
                          + (uint32_t)(sub & 1) * 16;
    const uint32_t aoBase = (uint32_t)(wm * 64 + lr + (sub & 1) * 8) * 48
                          + (uint32_t)(sub >> 1) * 16;

    for (int c = 0; c < NCHUNK; c++) {
        cp_wait<2>();          // groups beyond chunk c still pending: c+1, c+2
        __syncthreads();       // chunk c visible to all; all done consuming c-1

        const uint32_t st = sb + (uint32_t)(c & 3) * STAGE_BYTES;
        const uint32_t sAhi = st;
        const uint32_t sAlo = sAhi + ARR_BYTES;
        const uint32_t sBhi = sAlo + ARR_BYTES;
        const uint32_t sBlo = sBhi + ARR_BYTES;

        uint32_t bhi[4][2], blo[4][2];
        #pragma unroll
        for (int p = 0; p < 2; p++) {
            const uint32_t bo = boBase + (uint32_t)(p * 16) * 48;
            uint32_t t4[4];
            ldsm4(t4, sBhi + bo);
            bhi[2*p][0] = t4[0]; bhi[2*p][1] = t4[1]; bhi[2*p+1][0] = t4[2]; bhi[2*p+1][1] = t4[3];
            ldsm4(t4, sBlo + bo);
            blo[2*p][0] = t4[0]; blo[2*p][1] = t4[1]; blo[2*p+1][0] = t4[2]; blo[2*p+1][1] = t4[3];
        }
        #pragma unroll
        for (int mi = 0; mi < 4; mi++) {
            const uint32_t ao = aoBase + (uint32_t)(mi * 16) * 48;
            uint32_t ahi[4], alo[4];
            ldsm4(ahi, sAhi + ao);
            ldsm4(alo, sAlo + ao);
            #pragma unroll
            for (int ni = 0; ni < 4; ni++) {
                mma16816(acc[mi][ni], ahi, bhi[ni]);
                mma16816(acc[mi][ni], ahi, blo[ni]);
                mma16816(acc[mi][ni], alo, bhi[ni]);
            }
        }

        // issue loads for chunk c+3 into stage (c+3)&3 (consumed at iter c-1; all
        // warps are past that thanks to the sync above). Empty commit keeps the
        // group count uniform so cp_wait<2> stays correct at the tail.
        if (c + 3 < NCHUNK) {
            const uint32_t stn = sb + (uint32_t)((c + 3) & 3) * STAGE_BYTES;
            const int k0 = (c + 3) * KC;
            cpasync16(stn + 0 * ARR_BYTES + sOff, Ahi + gA + k0);
            cpasync16(stn + 1 * ARR_BYTES + sOff, Alo + gA + k0);
            cpasync16(stn + 2 * ARR_BYTES + sOff, Bhi + gB + k0);
            cpasync16(stn + 3 * ARR_BYTES + sOff, Blo + gB + k0);
        }
        cp_commit();
    }

    // -------- epilogue --------
    const int g = lane >> 2, t = lane & 3;
    float lb = 0.0f;
    if (MODE == 0) lb = lbp[0];

    #pragma unroll
    for (int mi = 0; mi < 4; mi++) {
        const int m0 = r0 + wm * 64 + mi * 16 + g;
        #pragma unroll
        for (int ni = 0; ni < 4; ni++) {
            const int nc = c0 + wn * 32 + ni * 8 + t * 2;
            float p0 = acc[mi][ni][0], p1 = acc[mi][ni][1];
            float p2 = acc[mi][ni][2], p3 = acc[mi][ni][3];
            if (MODE == 1) {
                const float b0 = bias_a[nc], b1 = bias_a[nc + 1];
                *(float2*)&outp[(size_t)m0 * DDIM + nc]       = make_float2(p0 + b0, p1 + b1);
                *(float2*)&outp[(size_t)(m0+8) * DDIM + nc]   = make_float2(p2 + b0, p3 + b1);
            } else {
                const int reg = nc >> 9;           // 0=u, 1=f, 2=gate
                const int lc = nc & 511;
                float b0, b1; float* dst;
                if (reg < 2) { b0 = bias_a[nc]; b1 = bias_a[nc + 1]; }
                else         { b0 = bias_b[lc]; b1 = bias_b[lc + 1]; }
                p0 += b0; p1 += b1; p2 += b0; p3 += b1;
                float o0, o1, o2, o3;
                if (reg == 0) {
                    o0 = p0 * sigm(p0); o1 = p1 * sigm(p1);
                    o2 = p2 * sigm(p2); o3 = p3 * sigm(p3);
                    dst = g_su;
                } else if (reg == 1) {
                    const float w = 1.0f - lb;
                    o0 = lb + w * sigm(p0); o1 = lb + w * sigm(p1);
                    o2 = lb + w * sigm(p2); o3 = lb + w * sigm(p3);
                    dst = g_lam;
                } else {
                    o0 = sigm(p0); o1 = sigm(p1); o2 = sigm(p2); o3 = sigm(p3);
                    dst = g_gate;
                }
                *(float2*)&dst[(size_t)m0 * DDIM + lc]     = make_float2(o0, o1);
                *(float2*)&dst[(size_t)(m0+8) * DDIM + lc] = make_float2(o2, o3);
            }
        }
    }
}

// ================= scan path =================
__global__ __launch_bounds__(256) void scan_phase1()
{
    int tt = blockIdx.x * blockDim.x + threadIdx.x;
    int chain = tt % CHAINS;
    int seg   = tt / CHAINS;
    int d = chain % DDIM, b = chain / DDIM;
    size_t base = ((size_t)(b * NSEQ + seg * SEGLEN)) * DDIM + d;

    float l[SEGLEN], v[SEGLEN];
    #pragma unroll
    for (int i = 0; i < SEGLEN; i++) {
        size_t idx = base + (size_t)i * DDIM;
        float li = g_lam[idx];
        float si = g_su[idx];
        l[i] = li;
        v[i] = (1.0f - li) * si;
    }
    float h = 0.0f, P = 1.0f;
    #pragma unroll
    for (int i = 0; i < SEGLEN; i++) { h = l[i] * h + v[i]; P *= l[i]; }
    float hr = 0.0f;
    #pragma unroll
    for (int i = SEGLEN - 1; i >= 0; i--) hr = l[i] * hr + v[i];

    size_t aidx = (size_t)seg * CHAINS + chain;
    g_aggA [aidx] = P;
    g_aggBf[aidx] = h;
    g_aggBr[aidx] = hr;
}
__global__ __launch_bounds__(256) void scan_phase2()
{
    int c = blockIdx.x * blockDim.x + threadIdx.x;
    float carry = 0.0f;
    #pragma unroll 8
    for (int s = 0; s < NSEG; s++) {
        size_t a = (size_t)s * CHAINS + c;
        g_cf[a] = carry;
        carry = g_aggA[a] * carry + g_aggBf[a];
    }
    carry = 0.0f;
    #pragma unroll 8
    for (int s = NSEG - 1; s >= 0; s--) {
        size_t a = (size_t)s * CHAINS + c;
        g_cr[a] = carry;
        carry = g_aggA[a] * carry + g_aggBr[a];
    }
}
__global__ __launch_bounds__(256) void scan_phase3()
{
    int tt = blockIdx.x * blockDim.x + threadIdx.x;
    int chain = tt % CHAINS;
    int seg   = tt / CHAINS;
    int d = chain % DDIM, b = chain / DDIM;
    size_t base = ((size_t)(b * NSEQ + seg * SEGLEN)) * DDIM + d;
    size_t aidx = (size_t)seg * CHAINS + chain;
    float cf = g_cf[aidx];
    float cr = g_cr[aidx];

    float l[SEGLEN], v[SEGLEN], hf[SEGLEN];
    #pragma unroll
    for (int i = 0; i < SEGLEN; i++) {
        size_t idx = base + (size_t)i * DDIM;
        float li = g_lam[idx];
        float si = g_su[idx];
        l[i] = li;
        v[i] = (1.0f - li) * si;
    }
    float h = cf;
    #pragma unroll
    for (int i = 0; i < SEGLEN; i++) { h = l[i] * h + v[i]; hf[i] = h; }
    float hr = cr;
    #pragma unroll
    for (int i = SEGLEN - 1; i >= 0; i--) {
        hr = l[i] * hr + v[i];
        g_h[base + (size_t)i * DDIM] = hf[i] + hr;
    }
}
__global__ __launch_bounds__(256) void rms_gate_kernel()
{
    int warp = threadIdx.x >> 5, lane = threadIdx.x & 31;
    int row = blockIdx.x * 8 + warp;
    size_t base = (size_t)row * DDIM + lane * 4;

    float4 hv[4];
    float ss = 0.0f;
    #pragma unroll
    for (int j = 0; j < 4; j++) {
        hv[j] = *(const float4*)&g_h[base + j * 128];
        ss += hv[j].x * hv[j].x + hv[j].y * hv[j].y + hv[j].z * hv[j].z + hv[j].w * hv[j].w;
    }
    #pragma unroll
    for (int o = 16; o > 0; o >>= 1) ss += __shfl_xor_sync(0xffffffff, ss, o);
    float scale = rsqrtf(ss * (1.0f / DDIM) + EPSV);

    #pragma unroll
    for (int j = 0; j < 4; j++) {
        float4 gv = *(const float4*)&g_gate[base + j * 128];
        float o0 = hv[j].x * scale * gv.x;
        float o1 = hv[j].y * scale * gv.y;
        float o2 = hv[j].z * scale * gv.z;
        float o3 = hv[j].w * scale * gv.w;
        __nv_bfloat16 h0 = __float2bfloat16_rn(o0), h1 = __float2bfloat16_rn(o1);
        __nv_bfloat16 h2 = __float2bfloat16_rn(o2), h3 = __float2bfloat16_rn(o3);
        __nv_bfloat16 l0 = __float2bfloat16_rn(o0 - __bfloat162float(h0));
        __nv_bfloat16 l1 = __float2bfloat16_rn(o1 - __bfloat162float(h1));
        __nv_bfloat16 l2 = __float2bfloat16_rn(o2 - __bfloat162float(h2));
        __nv_bfloat16 l3 = __float2bfloat16_rn(o3 - __bfloat162float(h3));
        uint2 uh; uh.x = pack_bf2(h0, h1); uh.y = pack_bf2(h2, h3);
        uint2 ul; ul.x = pack_bf2(l0, l1); ul.y = pack_bf2(l2, l3);
        *(uint2*)&g_hnhi[base + j * 128] = uh;
        *(uint2*)&g_hnlo[base + j * 128] = ul;
    }
}

// ================= launch =================
extern "C" void kernel_launch(void* const* d_in, const int* in_sizes, int n_in,
                              void* d_out, int out_size)
{
    const float* x    = (const float*)d_in[0];
    const float* lb   = (const float*)d_in[1];
    const float* Win  = (const float*)d_in[2];
    const float* bin  = (const float*)d_in[3];
    const float* Wg   = (const float*)d_in[4];
    const float* bg   = (const float*)d_in[5];
    const float* Wout = (const float*)d_in[6];
    const float* bout = (const float*)d_in[7];
    float* out = (float*)d_out;

    __nv_bfloat16 *xhi, *xlo, *b1hi, *b1lo, *b2hi, *b2lo, *hnhi, *hnlo;
    cudaGetSymbolAddress((void**)&xhi,  g_xhi);
    cudaGetSymbolAddress((void**)&xlo,  g_xlo);
    cudaGetSymbolAddress((void**)&b1hi, g_b1hi);
    cudaGetSymbolAddress((void**)&b1lo, g_b1lo);
    cudaGetSymbolAddress((void**)&b2hi, g_b2hi);
    cudaGetSymbolAddress((void**)&b2lo, g_b2lo);
    cudaGetSymbolAddress((void**)&hnhi, g_hnhi);
    cudaGetSymbolAddress((void**)&hnlo, g_hnlo);

    cudaFuncSetAttribute(gemm_tc<0>, cudaFuncAttributeMaxDynamicSharedMemorySize, SMEM_REQ);
    cudaFuncSetAttribute(gemm_tc<1>, cudaFuncAttributeMaxDynamicSharedMemorySize, SMEM_REQ);

    convert_x_kernel<<<(MTOT * DDIM / 4) / 256, 256>>>(x);
    convert_w1_kernel<<<(N1 * DDIM) / 256, 256>>>(Win, Wg);
    convert_w2_kernel<<<(DDIM * DDIM) / 256, 256>>>(Wout);

    dim3 g1(N1 / BN, MTOT / BM);           // (12, 512)
    gemm_tc<0><<<g1, 256, SMEM_REQ>>>(xhi, xlo, b1hi, b1lo, bin, bg, lb, nullptr);

    scan_phase1<<<SEGTOT / 256, 256>>>();
    scan_phase2<<<CHAINS / 256, 256>>>();
    scan_phase3<<<SEGTOT / 256, 256>>>();
    rms_gate_kernel<<<MTOT / 8, 256>>>();

    dim3 g2(DDIM / BN, MTOT / BM);         // (4, 512)
    gemm_tc<1><<<g2, 256, SMEM_REQ>>>(hnhi, hnlo, b2hi, b2lo, bout, nullptr, nullptr, out);
}